// round 14
// baseline (speedup 1.0000x reference)
#include <cuda_runtime.h>
#include <cuda_fp16.h>
#include <cstdint>

#define Bn   8
#define CHn  7
#define Hn   256
#define Wn   256
#define NBR  6
#define C1   64

#define CTAS_PER_BRANCH 1024
#define ITERS           8      // branch: 1024 CTAs * 4 warps * 16 px * 8 iters

#define MIX_CTAS        1024
#define MIX_ITERS       8      // mix: 1024 CTAs * 4 warps * 16 px * 8 iters

// Scratch for the "combined" (B,7,H,W) tensor between the two kernels.
__device__ float g_comb[Bn * CHn * Hn * Wn];

__device__ __forceinline__ uint32_t smem_u32(const void* p) {
    uint32_t a;
    asm("{ .reg .u64 t; cvta.to.shared.u64 t, %1; cvt.u32.u64 %0, t; }" : "=r"(a) : "l"(p));
    return a;
}
__device__ __forceinline__ unsigned packh2(float lo, float hi) {
    __half2 h = __floats2half2_rn(lo, hi);
    return *reinterpret_cast<unsigned*>(&h);
}
__device__ __forceinline__ void ldmatrix_x4(uint32_t r[4], uint32_t addr) {
    asm volatile("ldmatrix.sync.aligned.m8n8.x4.shared.b16 {%0,%1,%2,%3}, [%4];"
                 : "=r"(r[0]), "=r"(r[1]), "=r"(r[2]), "=r"(r[3]) : "r"(addr));
}
__device__ __forceinline__ void ldmatrix_x2(uint32_t r[2], uint32_t addr) {
    asm volatile("ldmatrix.sync.aligned.m8n8.x2.shared.b16 {%0,%1}, [%2];"
                 : "=r"(r[0]), "=r"(r[1]) : "r"(addr));
}
// fp16-accumulator MMA
__device__ __forceinline__ void mma16816_h(uint32_t c[2], const uint32_t a[4], const uint32_t b[2]) {
    asm volatile(
        "mma.sync.aligned.m16n8k16.row.col.f16.f16.f16.f16 "
        "{%0,%1}, {%2,%3,%4,%5}, {%6,%7}, {%0,%1};"
        : "+r"(c[0]), "+r"(c[1])
        : "r"(a[0]), "r"(a[1]), "r"(a[2]), "r"(a[3]), "r"(b[0]), "r"(b[1]));
}
// fp32-accumulator MMA
__device__ __forceinline__ void mma16816_f(float c[4], const uint32_t a[4], const uint32_t b[2]) {
    asm volatile(
        "mma.sync.aligned.m16n8k16.row.col.f32.f16.f16.f32 "
        "{%0,%1,%2,%3}, {%4,%5,%6,%7}, {%8,%9}, {%0,%1,%2,%3};"
        : "+f"(c[0]), "+f"(c[1]), "+f"(c[2]), "+f"(c[3])
        : "r"(a[0]), "r"(a[1]), "r"(a[2]), "r"(a[3]), "r"(b[0]), "r"(b[1]));
}

// Load one 3x3 window (zero-padded); interior path is unpredicated.
__device__ __forceinline__ void load_win(const float* __restrict__ xs,
                                         int hh0, int ww0, bool interior,
                                         float win[9])
{
    if (interior) {
        const float* pr = xs + (hh0 - 1) * Wn + (ww0 - 1);
        win[0] = __ldg(pr);          win[1] = __ldg(pr + 1);          win[2] = __ldg(pr + 2);
        win[3] = __ldg(pr + Wn);     win[4] = __ldg(pr + Wn + 1);     win[5] = __ldg(pr + Wn + 2);
        win[6] = __ldg(pr + 2 * Wn); win[7] = __ldg(pr + 2 * Wn + 1); win[8] = __ldg(pr + 2 * Wn + 2);
    } else {
        #pragma unroll
        for (int r = 0; r < 3; r++) {
            int hh = hh0 - 1 + r;
            bool hok = (hh >= 0) && (hh < Hn);
            #pragma unroll
            for (int cc = 0; cc < 3; cc++) {
                int ww = ww0 - 1 + cc;
                bool ok = hok && (ww >= 0) && (ww < Wn);
                win[r * 3 + cc] = ok ? __ldg(&xs[hh * Wn + ww]) : 0.f;
            }
        }
    }
}

// Load taps [t0, t1) of a 3x3 window (zero-padded).
__device__ __forceinline__ void load_taps(const float* __restrict__ xs,
                                          int hh0, int ww0, bool interior,
                                          int t0, int t1, float* dst)
{
    #pragma unroll 9
    for (int t = t0; t < t1; t++) {
        int r = t / 3, cc = t % 3;
        int hh = hh0 - 1 + r, ww = ww0 - 1 + cc;
        float val;
        if (interior) {
            val = __ldg(&xs[hh * Wn + ww]);
        } else {
            bool ok = (hh >= 0) && (hh < Hn) && (ww >= 0) && (ww < Wn);
            val = ok ? __ldg(&xs[hh * Wn + ww]) : 0.f;
        }
        dst[t - t0] = val;
    }
}

// ---------------------------------------------------------------------------
// Branch kernel (unchanged from R13 — measured ~70 us): warp-level HMMA,
// fp16 accumulators, software-pipelined LDG, double-buffered A.
// ---------------------------------------------------------------------------
__global__ __launch_bounds__(128) void branch_kernel(
    const float* __restrict__ x,
    const float* __restrict__ W1, const float* __restrict__ b1,
    const float* __restrict__ W2, const float* __restrict__ b2)
{
    __shared__ __half Bs[C1 * 40];
    __shared__ __half As[4][2][16 * 40];
    __shared__ float  w2s[C1];
    __shared__ float  sb2v;

    const int tid  = threadIdx.x;
    const int warp = tid >> 5;
    const int lane = tid & 31;
    const int n    = blockIdx.y;
    const int base_ic = (n < 3) ? 0 : 1;
    const int srcch   = (n < 3) ? n : n + 1;

    for (int i = tid; i < C1 * 40; i += 128) Bs[i] = __ushort_as_half(0);
    __syncthreads();
    for (int i = tid; i < C1 * 9; i += 128) {
        int c = i / 9, k = i % 9;
        Bs[c * 40 + k]      = __float2half_rn(W1[(((n * C1 + c) * 2 + base_ic) * 9) + k]);
        Bs[c * 40 + 16 + k] = __float2half_rn(W1[(((n * C1 + c) * 2 + (1 - base_ic)) * 9) + k]);
    }
    for (int c = tid; c < C1; c += 128) {
        Bs[c * 40 + 9] = __float2half_rn(b1[n * C1 + c]);
        w2s[c] = W2[n * C1 + c];
    }
    if (tid == 0) sb2v = b2[n];
    __syncthreads();

    uint32_t bf[8][2][2];
    {
        const uint32_t bbase = smem_u32(Bs);
        #pragma unroll
        for (int j = 0; j < 8; j++)
            #pragma unroll
            for (int s = 0; s < 2; s++) {
                int row = 8 * j + (lane & 7);
                uint32_t addr = bbase + (uint32_t)(row * 40 + s * 16) * 2
                              + (uint32_t)(((lane >> 3) & 1) * 16);
                ldmatrix_x2(bf[j][s], addr);
            }
    }
    unsigned w2h[8];
    #pragma unroll
    for (int j = 0; j < 8; j++) {
        int n0 = 8 * j + 2 * (lane & 3);
        w2h[j] = packh2(w2s[n0], w2s[n0 + 1]);
    }
    const float my_b2 = sb2v;

    const int p  = lane >> 1;
    const int ch = (lane & 1) ? srcch : 3;
    const int g  = lane >> 2;

    float win[9];
    {
        const int pixbase = (blockIdx.x * 4 + warp) * 16;
        const int pix = pixbase + p;
        const int b   = pix >> 16;
        const int hh0 = (pix >> 8) & 255;
        const int ww0 = pix & 255;
        const int tile_w = (pixbase >> 4) & 15;
        const bool interior = (hh0 >= 1) && (hh0 <= 254) && (tile_w >= 1) && (tile_w <= 14);
        const float* xs = x + ((size_t)(b * CHn + ch) << 16);
        load_win(xs, hh0, ww0, interior, win);
    }

    for (int it = 0; it < ITERS; it++) {
        const int pixbase = ((blockIdx.x + it * CTAS_PER_BRANCH) * 4 + warp) * 16;
        const int buf = it & 1;
        const uint32_t abase = smem_u32(&As[warp][buf][0]);

        unsigned hv0 = packh2(win[0], win[1]);
        unsigned hv1 = packh2(win[2], win[3]);
        unsigned hv2 = packh2(win[4], win[5]);
        unsigned hv3 = packh2(win[6], win[7]);
        unsigned hv4 = packh2(win[8], (lane & 1) ? 0.f : 1.0f);
        {
            __half* Arow = &As[warp][buf][p * 40 + (lane & 1) * 16];
            *reinterpret_cast<uint4*>(Arow)     = make_uint4(hv0, hv1, hv2, hv3);
            *reinterpret_cast<uint4*>(Arow + 8) = make_uint4(hv4, 0u, 0u, 0u);
        }

        float cenC0 = __shfl_sync(0xFFFFFFFFu, win[4], (g << 1) | 1);
        float cenC1 = __shfl_sync(0xFFFFFFFFu, win[4], ((g + 8) << 1) | 1);
        float cenB0 = 0.f, cenB1 = 0.f;
        if (n == 0) {
            cenB0 = __shfl_sync(0xFFFFFFFFu, win[4], g << 1);
            cenB1 = __shfl_sync(0xFFFFFFFFu, win[4], (g + 8) << 1);
        }
        __syncwarp();

        uint32_t a0[4], a1[4];
        {
            int row = lane & 15;
            uint32_t addr = abase + (uint32_t)(row * 40) * 2 + (uint32_t)((lane >> 4) * 16);
            ldmatrix_x4(a0, addr);
            ldmatrix_x4(a1, addr + 32);
        }

        if (it + 1 < ITERS) {
            const int pbN = ((blockIdx.x + (it + 1) * CTAS_PER_BRANCH) * 4 + warp) * 16;
            const int pixN = pbN + p;
            const int bN   = pixN >> 16;
            const int hh0N = (pixN >> 8) & 255;
            const int ww0N = pixN & 255;
            const int tile_wN = (pbN >> 4) & 15;
            const bool interiorN = (hh0N >= 1) && (hh0N <= 254) && (tile_wN >= 1) && (tile_wN <= 14);
            const float* xsN = x + ((size_t)(bN * CHn + ch) << 16);
            load_win(xsN, hh0N, ww0N, interiorN, win);
        }

        uint32_t c[8][2];
        #pragma unroll
        for (int j = 0; j < 8; j++) {
            c[j][0] = 0u; c[j][1] = 0u;
            mma16816_h(c[j], a0, bf[j][0]);
            mma16816_h(c[j], a1, bf[j][1]);
        }

        const __half2 zero2 = __floats2half2_rn(0.f, 0.f);
        __half2 aA0 = zero2, aA1 = zero2, aB0 = zero2, aB1 = zero2;
        #pragma unroll
        for (int j = 0; j < 8; j++) {
            __half2 w2v = *reinterpret_cast<__half2*>(&w2h[j]);
            __half2 rA = __hmax2(*reinterpret_cast<__half2*>(&c[j][0]), zero2);
            __half2 rB = __hmax2(*reinterpret_cast<__half2*>(&c[j][1]), zero2);
            if (j & 1) { aA1 = __hfma2(w2v, rA, aA1); aB1 = __hfma2(w2v, rB, aB1); }
            else       { aA0 = __hfma2(w2v, rA, aA0); aB0 = __hfma2(w2v, rB, aB0); }
        }
        float2 fA0 = __half22float2(aA0), fA1 = __half22float2(aA1);
        float2 fB0 = __half22float2(aB0), fB1 = __half22float2(aB1);
        float simA = (fA0.x + fA0.y) + (fA1.x + fA1.y);
        float simB = (fB0.x + fB0.y) + (fB1.x + fB1.y);
        simA += __shfl_xor_sync(0xFFFFFFFFu, simA, 1);
        simB += __shfl_xor_sync(0xFFFFFFFFu, simB, 1);
        simA += __shfl_xor_sync(0xFFFFFFFFu, simA, 2);
        simB += __shfl_xor_sync(0xFFFFFFFFu, simB, 2);

        if ((lane & 3) == 0) {
            int pixA = pixbase + g;
            int pixB = pixbase + g + 8;
            float resA = cenC0 / (1.f + __expf(-(simA + my_b2)));
            float resB = cenC1 / (1.f + __expf(-(simB + my_b2)));
            int bA = pixA >> 16, hwA = pixA & 65535;
            int bB = pixB >> 16, hwB = pixB & 65535;
            g_comb[((size_t)(bA * CHn + srcch) << 16) + hwA] = resA;
            g_comb[((size_t)(bB * CHn + srcch) << 16) + hwB] = resB;
            if (n == 0) {
                g_comb[((size_t)(bA * CHn + 3) << 16) + hwA] = cenB0;
                g_comb[((size_t)(bB * CHn + 3) << 16) + hwB] = cenB1;
            }
        }
    }
}

// ---------------------------------------------------------------------------
// Mix kernel: HMMA implicit GEMM. out[16px, 8ch] = A[16px,64] . B[8,64]^T.
// A (im2col of g_comb): k = ic*9+tap for ic 0..6, k63 = 1.0 (bias lane).
// B row o (o<7): Wm[o,ic,tap]; k63 = bm[o]; row 7 = 0.
// fp16 inputs, fp32 accumulation. Row stride 72 halves (144B):
// 4*row mod 32 distinct per 8-row matrix -> conflict-free ldmatrix.
// ---------------------------------------------------------------------------
__global__ __launch_bounds__(128) void mix_kernel(
    const float* __restrict__ Wm, const float* __restrict__ bm,
    float* __restrict__ out)
{
    __shared__ __half Bs[8 * 72];            // 1152 B
    __shared__ __half As[4][16 * 72];        // 4 x 2304 B

    const int tid  = threadIdx.x;
    const int warp = tid >> 5;
    const int lane = tid & 31;

    // ---- stage B ----
    for (int i = tid; i < 8 * 72; i += 128) Bs[i] = __ushort_as_half(0);
    __syncthreads();
    for (int i = tid; i < 7 * 63; i += 128) {
        int o = i / 63, k = i % 63;
        Bs[o * 72 + k] = __float2half_rn(Wm[i]);
    }
    if (tid < 7) Bs[tid * 72 + 63] = __float2half_rn(bm[tid]);
    __syncthreads();

    // ---- B fragments (4 k-steps, N=8) ----
    uint32_t bfm[4][2];
    {
        const uint32_t bbase = smem_u32(Bs);
        #pragma unroll
        for (int kq = 0; kq < 4; kq++) {
            uint32_t addr = bbase + (uint32_t)((lane & 7) * 72) * 2
                          + (uint32_t)(kq * 32) + (uint32_t)(((lane >> 3) & 1) * 16);
            ldmatrix_x2(bfm[kq], addr);
        }
    }

    const int p    = lane >> 1;      // pixel within tile
    const int half = lane & 1;       // k-half: 0 -> k0..31, 1 -> k32..63
    const uint32_t abase = smem_u32(&As[warp][0]);

    for (int it = 0; it < MIX_ITERS; it++) {
        const int pixbase = ((blockIdx.x + it * MIX_CTAS) * 4 + warp) * 16;
        const int pix = pixbase + p;
        const int b   = pix >> 16;
        const int hh0 = (pix >> 8) & 255;
        const int ww0 = pix & 255;
        const int tile_w = (pixbase >> 4) & 15;
        const bool interior = (hh0 >= 1) && (hh0 <= 254) && (tile_w >= 1) && (tile_w <= 14);
        const float* cb = g_comb + ((size_t)(b * CHn) << 16);

        // ---- im2col: 32 k-values per thread ----
        float v[32];
        if (half == 0) {
            // ch0, ch1, ch2 full; ch3 taps 0..4
            load_taps(cb,               hh0, ww0, interior, 0, 9, &v[0]);
            load_taps(cb + (1 << 16),   hh0, ww0, interior, 0, 9, &v[9]);
            load_taps(cb + (2 << 16),   hh0, ww0, interior, 0, 9, &v[18]);
            load_taps(cb + (3 << 16),   hh0, ww0, interior, 0, 5, &v[27]);
        } else {
            // ch3 taps 5..8; ch4, ch5, ch6 full; bias
            load_taps(cb + (3 << 16),   hh0, ww0, interior, 5, 9, &v[0]);
            load_taps(cb + (4 << 16),   hh0, ww0, interior, 0, 9, &v[4]);
            load_taps(cb + (5 << 16),   hh0, ww0, interior, 0, 9, &v[13]);
            load_taps(cb + (6 << 16),   hh0, ww0, interior, 0, 9, &v[22]);
            v[31] = 1.0f;
        }

        // pack -> STS (4 x uint4)
        {
            __half* Arow = &As[warp][p * 72 + half * 32];
            #pragma unroll
            for (int q = 0; q < 4; q++) {
                unsigned u0 = packh2(v[q * 8 + 0], v[q * 8 + 1]);
                unsigned u1 = packh2(v[q * 8 + 2], v[q * 8 + 3]);
                unsigned u2 = packh2(v[q * 8 + 4], v[q * 8 + 5]);
                unsigned u3 = packh2(v[q * 8 + 6], v[q * 8 + 7]);
                *reinterpret_cast<uint4*>(Arow + q * 8) = make_uint4(u0, u1, u2, u3);
            }
        }
        __syncwarp();

        // ---- A fragments + 4 MMA (fp32 accum) ----
        float c[4] = {0.f, 0.f, 0.f, 0.f};
        {
            int row = lane & 15;
            uint32_t raddr = abase + (uint32_t)(row * 72) * 2 + (uint32_t)((lane >> 4) * 16);
            #pragma unroll
            for (int kq = 0; kq < 4; kq++) {
                uint32_t a[4];
                ldmatrix_x4(a, raddr + kq * 32);
                mma16816_f(c, a, bfm[kq]);
            }
        }

        // ---- store: lane holds rows (lane>>2, +8), cols 2*(lane&3), +1 ----
        {
            const int r  = lane >> 2;
            const int o0 = 2 * (lane & 3);
            const int hwbase = pixbase & 65535;
            const int bb = pixbase >> 16;
            float* ob = out + ((size_t)(bb * CHn) << 16);
            if (o0 < 7) {
                ob[((size_t)o0 << 16) + hwbase + r]     = c[0];
                ob[((size_t)o0 << 16) + hwbase + r + 8] = c[2];
            }
            if (o0 + 1 < 7) {
                ob[((size_t)(o0 + 1) << 16) + hwbase + r]     = c[1];
                ob[((size_t)(o0 + 1) << 16) + hwbase + r + 8] = c[3];
            }
        }
        __syncwarp();
    }
}

// ---------------------------------------------------------------------------
// kernel_launch: graph-capturable, allocation-free.
// Input order (metadata): x, W1, b1, W2, b2, Wm, bm
// ---------------------------------------------------------------------------
extern "C" void kernel_launch(void* const* d_in, const int* in_sizes, int n_in,
                              void* d_out, int out_size)
{
    const float* x  = (const float*)d_in[0];
    const float* W1 = (const float*)d_in[1];
    const float* b1 = (const float*)d_in[2];
    const float* W2 = (const float*)d_in[3];
    const float* b2 = (const float*)d_in[4];
    const float* Wm = (const float*)d_in[5];
    const float* bm = (const float*)d_in[6];
    float* out = (float*)d_out;

    dim3 gridB(CTAS_PER_BRANCH, NBR, 1);
    branch_kernel<<<gridB, 128>>>(x, W1, b1, W2, b2);

    mix_kernel<<<MIX_CTAS, 128>>>(Wm, bm, out);
}